// round 9
// baseline (speedup 1.0000x reference)
#include <cuda_runtime.h>
#include <cuda_bf16.h>
#include <math.h>

// Problem constants (fixed by reference: x,y (4,2,32768) fp32, max_shift=128)
constexpr int T  = 32768;
constexpr int P  = 8;      // B*C pairs
constexpr int MS = 128;    // max_shift
constexpr int S  = 2 * MS + 1;  // 257 shifts

// Tiling: 512 blocks (64 chunks x 8 pairs) of 264 threads (R7 geometry)
constexpr int CHK    = 512;
constexpr int NCHUNK = T / CHK;   // 64
constexpr int Z      = 8;         // time-slices per block
constexpr int G      = 33;        // shift groups of 8 -> covers shifts 0..263
constexpr int BD     = Z * G;     // 264 threads
constexpr int STEPS  = CHK / Z;   // 64 timesteps per thread
constexpr int KK     = STEPS / 4; // 16 double-pair iterations
constexpr int XH     = CHK + 272; // 784 floats: x tile + halo

typedef unsigned long long ull;

__device__ __forceinline__ void fma2(ull& a, ull y, ull x) {
    asm("fma.rn.f32x2 %0, %1, %2, %0;" : "+l"(a) : "l"(y), "l"(x));
}
__device__ __forceinline__ float unpack_sum(ull a) {
    float lo = __uint_as_float((unsigned)(a & 0xffffffffu));
    float hi = __uint_as_float((unsigned)(a >> 32));
    return lo + hi;
}

// Scratch (atomic-free data, atomic completion counters)
__device__ float g_part[P][NCHUNK][264];   // [pair][chunk][shift]
__device__ float g_stats[P][NCHUNK][4];    // [pair][chunk][{Sy,Syy,Sx,Sxx}]
__device__ int   g_cnt[P];                 // zero-init; reset in-kernel for replay

__global__ __launch_bounds__(BD, 4) void corr_fused(const float* __restrict__ x,
                                                    const float* __restrict__ y,
                                                    float* __restrict__ out) {
    __shared__ __align__(16) float smxA[XH];   // smxA[i] = x_pad[cbase + i]
    __shared__ __align__(16) float smxB[XH];   // smxB[i] = smxA[i + 1]  (odd-pair copy)
    __shared__ __align__(16) float smy[CHK];
    __shared__ float red[Z][G][8];
    __shared__ float wstats[8][4];
    __shared__ int   isLast;
    __shared__ float2 scH[MS], scT[MS];        // boundary prefix sums (x, x^2)
    __shared__ float tot[4];

    const int chunk = blockIdx.x;
    const int pair  = blockIdx.y;
    const float* xp = x + pair * T;
    const float* yp = y + pair * T;
    const int cbase = chunk * CHK;
    const int tid   = threadIdx.x;

    // ---- load tiles: A copy (aligned) + B copy (shifted by one float) ----
    if (chunk >= 1 && chunk <= NCHUNK - 2) {
        if (tid < XH / 4) {
            const float4 v = reinterpret_cast<const float4*>(xp + cbase - MS)[tid];
            reinterpret_cast<float4*>(smxA)[tid] = v;
            const int b = 4 * tid;
            if (b > 0) smxB[b - 1] = v.x;
            smxB[b]     = v.y;
            smxB[b + 1] = v.z;
            smxB[b + 2] = v.w;
        }
    } else {
        for (int i = tid; i < XH; i += BD) {
            int gi = cbase - MS + i;
            float v = (gi >= 0 && gi < T) ? xp[gi] : 0.0f;
            smxA[i] = v;
            if (i > 0) smxB[i - 1] = v;
        }
    }
    {
        const float4* yg = reinterpret_cast<const float4*>(yp + cbase);
        if (tid < CHK / 4) reinterpret_cast<float4*>(smy)[tid] = yg[tid];
    }
    __syncthreads();

    // ---- per-chunk statistics (first 8 warps, 2 elements each) ----
    if (tid < 256) {
        float ly = 0.f, lyy = 0.f, lx = 0.f, lxx = 0.f;
        #pragma unroll
        for (int r = 0; r < CHK / 256; r++) {
            int i = tid + 256 * r;
            float yv = smy[i];       ly += yv; lyy = fmaf(yv, yv, lyy);
            float xv = smxA[MS + i]; lx += xv; lxx = fmaf(xv, xv, lxx);
        }
        #pragma unroll
        for (int o = 16; o; o >>= 1) {
            ly  += __shfl_down_sync(0xffffffffu, ly,  o);
            lyy += __shfl_down_sync(0xffffffffu, lyy, o);
            lx  += __shfl_down_sync(0xffffffffu, lx,  o);
            lxx += __shfl_down_sync(0xffffffffu, lxx, o);
        }
        if ((tid & 31) == 0) {
            int w = tid >> 5;
            wstats[w][0] = ly; wstats[w][1] = lyy;
            wstats[w][2] = lx; wstats[w][3] = lxx;
        }
    }

    // ---- shifted dot products: packed f32x2, 8 shifts/thread ----
    // even shift 8g+2m: acc[2m]   += (y[2k],y[2k+1]) * PA_{d0+m+k}
    // odd  shift 8g+2m+1: acc[2m+1] += (y[2k],y[2k+1]) * PB_{d0+m+k}
    // where PA_j = (xA[2j], xA[2j+1]), PB_j = (xB[2j], xB[2j+1]) = (xA[2j+1], xA[2j+2])
    const int g  = tid % G;          // shift group: shifts [8g, 8g+8)
    const int tz = tid / G;          // time slice
    const int d2 = tz * 16 + 2 * g;  // ulonglong2 index of PA pair-pair window base
    const int yb = tz * 16;          // ulonglong2 index of y window base

    const ulonglong2* LA = reinterpret_cast<const ulonglong2*>(smxA);
    const ulonglong2* LB = reinterpret_cast<const ulonglong2*>(smxB);
    const ulonglong2* LY = reinterpret_cast<const ulonglong2*>(smy);

    ull acc[8];
    #pragma unroll
    for (int j = 0; j < 8; j++) acc[j] = 0ull;

    ull PA[6], PB[6];
    {
        ulonglong2 a01 = LA[d2],     a23 = LA[d2 + 1];
        ulonglong2 b01 = LB[d2],     b23 = LB[d2 + 1];
        PA[0] = a01.x; PA[1] = a01.y; PA[2] = a23.x; PA[3] = a23.y;
        PB[0] = b01.x; PB[1] = b01.y; PB[2] = b23.x; PB[3] = b23.y;
    }

    #pragma unroll
    for (int kk = 0; kk < KK; ++kk) {
        const ulonglong2 an = LA[d2 + kk + 2];
        const ulonglong2 bn = LB[d2 + kk + 2];
        const ulonglong2 yy = LY[yb + kk];
        PA[4] = an.x; PA[5] = an.y;
        PB[4] = bn.x; PB[5] = bn.y;

        #pragma unroll
        for (int m = 0; m < 4; m++) {
            fma2(acc[2 * m],     yy.x, PA[m]);
            fma2(acc[2 * m + 1], yy.x, PB[m]);
            fma2(acc[2 * m],     yy.y, PA[m + 1]);
            fma2(acc[2 * m + 1], yy.y, PB[m + 1]);
        }
        // slide window by 2 pairs (renamed under full unroll)
        PA[0] = PA[2]; PA[1] = PA[3]; PA[2] = PA[4]; PA[3] = PA[5];
        PB[0] = PB[2]; PB[1] = PB[3]; PB[2] = PB[4]; PB[3] = PB[5];
    }

    #pragma unroll
    for (int j = 0; j < 8; j++) red[tz][g][j] = unpack_sum(acc[j]);
    __syncthreads();

    // 264 threads: one (g, j) each, sum over Z slices
    {
        const int gg = tid >> 3;
        const int j  = tid & 7;
        float s = 0.f;
        #pragma unroll
        for (int z = 0; z < Z; z++) s += red[z][gg][j];
        g_part[pair][chunk][tid] = s;
    }
    if (tid >= 256 && tid < 260) {
        int j = tid - 256;
        float s = 0.f;
        #pragma unroll
        for (int w = 0; w < 8; w++) s += wstats[w][j];
        g_stats[pair][chunk][j] = s;
    }
    __syncthreads();

    // ---- completion handshake: last block of this pair finalizes ----
    if (tid == 0) {
        __threadfence();
        int old = atomicAdd(&g_cnt[pair], 1);
        isLast = (old == NCHUNK - 1) ? 1 : 0;
    }
    __syncthreads();
    if (!isLast) return;
    __threadfence();

    // =================== FINALIZE (one block per pair) ===================
    if (tid < MS) {
        float v = xp[tid];
        scH[tid] = make_float2(v, v * v);
    } else if (tid < 2 * MS) {
        int j = tid - MS;
        float v = xp[T - 1 - j];
        scT[j] = make_float2(v, v * v);
    }
    // warp 0 (full warp) gathers per-chunk stats: lanes sum chunks lane, lane+32
    if (tid < 32) {
        float4 a = *reinterpret_cast<const float4*>(g_stats[pair][tid]);
        float4 b = *reinterpret_cast<const float4*>(g_stats[pair][tid + 32]);
        a.x += b.x; a.y += b.y; a.z += b.z; a.w += b.w;
        #pragma unroll
        for (int o = 16; o; o >>= 1) {
            a.x += __shfl_down_sync(0xffffffffu, a.x, o);
            a.y += __shfl_down_sync(0xffffffffu, a.y, o);
            a.z += __shfl_down_sync(0xffffffffu, a.z, o);
            a.w += __shfl_down_sync(0xffffffffu, a.w, o);
        }
        if (tid == 0) { tot[0] = a.x; tot[1] = a.y; tot[2] = a.z; tot[3] = a.w; }
    }
    __syncthreads();

    // Hillis-Steele inclusive scans over head and reversed tail (128 each)
    #pragma unroll
    for (int o = 1; o < MS; o <<= 1) {
        float2 v = make_float2(0.f, 0.f);
        const bool act = tid < 2 * MS;
        float2* arr = (tid < MS) ? scH : scT;
        const int j = (tid < MS) ? tid : tid - MS;
        if (act) {
            v = arr[j];
            if (j >= o) { v.x += arr[j - o].x; v.y += arr[j - o].y; }
        }
        __syncthreads();
        if (act) arr[j] = v;
        __syncthreads();
    }

    // ---- per-shift final Pearson value ----
    if (tid < S) {
        const float Sy  = tot[0], Syy = tot[1];
        const float Sx  = tot[2], Sxx = tot[3];
        const float invT = 1.0f / (float)T;
        const float my   = Sy * invT;
        const float vyy  = Syy - my * Sy;     // sum((y - my)^2)

        float part = 0.f;
        #pragma unroll
        for (int c = 0; c < NCHUNK; c++) part += g_part[pair][c][tid];

        const int d = tid - MS;
        float bx = 0.f, bxx = 0.f;
        if (d > 0)      { float2 h = scH[d - 1];   bx = h.x;  bxx = h.y; }
        else if (d < 0) { float2 t2 = scT[-d - 1]; bx = t2.x; bxx = t2.y; }

        const float wsx  = Sx  - bx;
        const float wsxx = Sxx - bxx;
        const float num  = part - my * wsx;           // sum(xw * yc)
        const float vxx  = wsxx - wsx * wsx * invT;   // sum((xw - mean_xw)^2)
        out[tid * P + pair] = num * rsqrtf(vxx * vyy);
    }

    __syncthreads();
    if (tid == 0) g_cnt[pair] = 0;   // reset for next graph replay
}

extern "C" void kernel_launch(void* const* d_in, const int* in_sizes, int n_in,
                              void* d_out, int out_size) {
    const float* x = (const float*)d_in[0];
    const float* y = (const float*)d_in[1];
    float* out = (float*)d_out;

    corr_fused<<<dim3(NCHUNK, P), BD>>>(x, y, out);
}